// round 12
// baseline (speedup 1.0000x reference)
#include <cuda_runtime.h>
#include <math.h>

// Problem constants (fixed by the reference)
#define NN 6000          // N_USERS + N_ITEMS
#define NNP 6016         // padded row count (multiple of 64) for tiled GEMM
#define EE 100000        // edges
#define NREL 2

// ---------------------------------------------------------------------------
// Device scratch (static device globals — zero-initialized, no runtime alloc)
// ---------------------------------------------------------------------------
__device__ int   g_cnt[NN];
__device__ int   g_rowptr[NN + 1];
__device__ int   g_cursor[NN];
__device__ int   g_ssrc[EE];        // CSR (by dst): source node per slot
__device__ int   g_stype[EE];       // CSR: edge type per slot

__device__ float g_W0[2 * NN * 32]; // layer-0 relation weights W[r][n][o]
__device__ float g_HRa[NN * 192];   // HR ping
__device__ float g_HRb[NN * 192];   // HR pong
__device__ float g_x3[NN * 32];     // layer-3 output (GAT input)
__device__ float g_h[NN * 512];     // GAT h
__device__ float g_xb[NNP * 512];   // GAT output (padded rows stay 0)
__device__ float g_WcAll[6144 + 12288 + 6144]; // fused weights layers 1..3
__device__ float g_asv[NN];
__device__ float g_adv[NN];
__device__ float g_A[NNP * 128];    // x @ w1[0:512]
__device__ float g_B[NNP * 128];    // x @ w1[512:1024]

#define WC1_OFF 0
#define WC2_OFF 6144
#define WC3_OFF 18432

__device__ __forceinline__ float lrelu(float x) { return x > 0.f ? x : 0.2f * x; }

__device__ __forceinline__ float tanh_ap(float x) {
    float r;
    asm("tanh.approx.f32 %0, %1;" : "=f"(r) : "f"(x));
    return r;
}

typedef unsigned long long ull;
__device__ __forceinline__ ull pk2(float lo, float hi) {
    ull r; asm("mov.b64 %0, {%1, %2};" : "=l"(r) : "f"(lo), "f"(hi)); return r;
}
__device__ __forceinline__ void upk2(float& lo, float& hi, ull v) {
    asm("mov.b64 {%0, %1}, %2;" : "=f"(lo), "=f"(hi) : "l"(v));
}
__device__ __forceinline__ void fma2(ull& c, ull a, ull b) {
    asm("fma.rn.f32x2 %0, %1, %2, %0;" : "+l"(c) : "l"(a), "l"(b));
}

// ---------------------------------------------------------------------------
// CSR build. g_cnt starts zero (static init first run; k_scan re-zeroes it
// after consuming, keeping every subsequent replay correct).
// ---------------------------------------------------------------------------
__global__ void k_hist(const int* __restrict__ dst) {
    int e = blockIdx.x * blockDim.x + threadIdx.x;
    if (e < EE) atomicAdd(&g_cnt[dst[e]], 1);
}

__global__ void k_scan() {
    __shared__ int sp[256];
    int tid = threadIdx.x;
    const int CH = (NN + 255) / 256;   // 24
    int base = tid * CH;
    int s = 0;
    for (int i = 0; i < CH; i++) {
        int idx = base + i;
        if (idx < NN) s += g_cnt[idx];
    }
    sp[tid] = s;
    __syncthreads();
    for (int off = 1; off < 256; off <<= 1) {
        int v = 0;
        if (tid >= off) v = sp[tid - off];
        __syncthreads();
        sp[tid] += v;
        __syncthreads();
    }
    int run = sp[tid] - s;  // exclusive prefix for this chunk
    for (int i = 0; i < CH; i++) {
        int idx = base + i;
        if (idx < NN) {
            int c = g_cnt[idx];
            g_rowptr[idx] = run;
            g_cursor[idx] = run;
            g_cnt[idx] = 0;          // reset for next replay
            run += c;
        }
    }
    if (tid == 255) g_rowptr[NN] = sp[255];
}

__global__ void k_scatter(const int* __restrict__ src, const int* __restrict__ dst,
                          const int* __restrict__ et) {
    int e = blockIdx.x * blockDim.x + threadIdx.x;
    if (e < EE) {
        int p = atomicAdd(&g_cursor[dst[e]], 1);
        g_ssrc[p]  = src[e];
        g_stype[p] = et[e];
    }
}

// ---------------------------------------------------------------------------
// Prep: W0 for layer 0; fused Wcat for layers 1..3.
// ---------------------------------------------------------------------------
__device__ __forceinline__ float wcat_elem(const float* __restrict__ basis,
                                           const float* __restrict__ comp,
                                           const float* __restrict__ root,
                                           int IN, int OUT, int i) {
    int J = 3 * OUT;
    int k = i / J;
    int j = i - k * J;
    if (j < 2 * OUT) {
        int r = j / OUT;
        int o = j - r * OUT;
        float v = 0.f;
#pragma unroll
        for (int b = 0; b < 4; b++)
            v += comp[r * 4 + b] * basis[(b * IN + k) * OUT + o];
        return v;
    }
    return root[k * OUT + (j - 2 * OUT)];
}

__global__ void k_prep(const float* __restrict__ basis0, const float* __restrict__ comp0,
                       const float* __restrict__ basis1, const float* __restrict__ comp1,
                       const float* __restrict__ root1,
                       const float* __restrict__ basis2, const float* __restrict__ comp2,
                       const float* __restrict__ root2,
                       const float* __restrict__ basis3, const float* __restrict__ comp3,
                       const float* __restrict__ root3) {
    int i = blockIdx.x * blockDim.x + threadIdx.x;
    if (i < 2 * NN * 32) {
        int r   = i / (NN * 32);
        int rem = i - r * (NN * 32);
        int n   = rem >> 5;
        int o   = rem & 31;
        float v = 0.f;
#pragma unroll
        for (int b = 0; b < 4; b++)
            v += comp0[r * 4 + b] * basis0[(b * NN + n) * 32 + o];
        g_W0[i] = v;
        return;
    }
    int j = i - 2 * NN * 32;
    if (j < 6144) { g_WcAll[WC1_OFF + j] = wcat_elem(basis1, comp1, root1, 32, 64, j); return; }
    j -= 6144;
    if (j < 12288) { g_WcAll[WC2_OFF + j] = wcat_elem(basis2, comp2, root2, 64, 64, j); return; }
    j -= 12288;
    if (j < 6144) { g_WcAll[WC3_OFF + j] = wcat_elem(basis3, comp3, root3, 64, 32, j); }
}

// ---------------------------------------------------------------------------
// Layer 0 (x = I) fused with HR1 = x0 @ Wcat1. x0 never hits global memory.
// Warp per node; lane owns x0 col `lane`; HR1 cols via warp shuffles.
// ---------------------------------------------------------------------------
__global__ void k_l0(const float* __restrict__ root0, const float* __restrict__ rbias0) {
    int warp = (blockIdx.x * blockDim.x + threadIdx.x) >> 5;
    int lane = threadIdx.x & 31;
    if (warp >= NN) return;
    int n = warp;
    int beg = g_rowptr[n], end = g_rowptr[n + 1];
    float a0 = 0.f, a1 = 0.f;
    int c0 = 0, c1 = 0;
    for (int e = beg; e < end; e++) {
        int s = g_ssrc[e];
        int t = g_stype[e];
        float v = g_W0[(t * NN + s) * 32 + lane];
        if (t == 0) { a0 += v; c0++; } else { a1 += v; c1++; }
    }
    float x = tanh_ap(root0[n * 32 + lane] + rbias0[lane]
                    + a0 / fmaxf((float)c0, 1.f) + a1 / fmaxf((float)c1, 1.f));
    // HR1[n, 192] = x0[n,:] @ Wcat1  (6 cols per lane)
    float acc[6] = {0.f, 0.f, 0.f, 0.f, 0.f, 0.f};
    const float* W = g_WcAll + WC1_OFF;
#pragma unroll 4
    for (int k = 0; k < 32; k++) {
        float xk = __shfl_sync(0xffffffffu, x, k);
        const float* wr = W + k * 192;
#pragma unroll
        for (int j = 0; j < 6; j++) acc[j] += xk * wr[lane + j * 32];
    }
#pragma unroll
    for (int j = 0; j < 6; j++) g_HRa[n * 192 + lane + j * 32] = acc[j];
}

// ---------------------------------------------------------------------------
// Fused RGCN agg (OUT=64) + next-layer HR (x stays in registers; shuffles).
// Warp per node: lane owns x cols {lane, lane+32}.
// ---------------------------------------------------------------------------
template <int J2, int NCOL2>
__global__ void k_agg64(const float* __restrict__ rbias,
                        const float* __restrict__ HRin, float* __restrict__ HRout,
                        int wcoff) {
    int warp = (blockIdx.x * blockDim.x + threadIdx.x) >> 5;
    int lane = threadIdx.x & 31;
    if (warp >= NN) return;
    int n = warp;
    int beg = g_rowptr[n], end = g_rowptr[n + 1];
    float a0[2] = {0.f, 0.f}, a1[2] = {0.f, 0.f};
    int c0 = 0, c1 = 0;
    for (int e = beg; e < end; e++) {
        int s = g_ssrc[e];
        int t = g_stype[e];
        const float* hrow = HRin + s * 192 + t * 64;
        if (t == 0) {
            c0++; a0[0] += hrow[lane]; a0[1] += hrow[lane + 32];
        } else {
            c1++; a1[0] += hrow[lane]; a1[1] += hrow[lane + 32];
        }
    }
    float i0 = 1.f / fmaxf((float)c0, 1.f);
    float i1 = 1.f / fmaxf((float)c1, 1.f);
    float xlo = tanh_ap(HRin[n * 192 + 128 + lane]      + rbias[lane]      + a0[0] * i0 + a1[0] * i1);
    float xhi = tanh_ap(HRin[n * 192 + 128 + lane + 32] + rbias[lane + 32] + a0[1] * i0 + a1[1] * i1);
    // HRnext[n, J2] = x[n,:64] @ Wnext
    float acc[NCOL2];
#pragma unroll
    for (int j = 0; j < NCOL2; j++) acc[j] = 0.f;
    const float* W = g_WcAll + wcoff;
#pragma unroll 4
    for (int k = 0; k < 64; k++) {
        float xk = (k < 32) ? __shfl_sync(0xffffffffu, xlo, k)
                            : __shfl_sync(0xffffffffu, xhi, k - 32);
        const float* wr = W + k * J2;
#pragma unroll
        for (int j = 0; j < NCOL2; j++) acc[j] += xk * wr[lane + j * 32];
    }
#pragma unroll
    for (int j = 0; j < NCOL2; j++) HRout[n * J2 + lane + j * 32] = acc[j];
}

// Layer-3 agg (OUT=32): writes g_x3 for the GAT stage.
__global__ void k_agg3(const float* __restrict__ rbias) {
    int warp = (blockIdx.x * blockDim.x + threadIdx.x) >> 5;
    int lane = threadIdx.x & 31;
    if (warp >= NN) return;
    int n = warp;
    int beg = g_rowptr[n], end = g_rowptr[n + 1];
    float a0 = 0.f, a1 = 0.f;
    int c0 = 0, c1 = 0;
    for (int e = beg; e < end; e++) {
        int s = g_ssrc[e];
        int t = g_stype[e];
        float v = g_HRa[s * 96 + t * 32 + lane];
        if (t == 0) { a0 += v; c0++; } else { a1 += v; c1++; }
    }
    float o = g_HRa[n * 96 + 64 + lane] + rbias[lane]
            + a0 / fmaxf((float)c0, 1.f) + a1 / fmaxf((float)c1, 1.f);
    g_x3[n * 32 + lane] = tanh_ap(o);
}

// ---------------------------------------------------------------------------
// GAT h = x3 @ gat_w (32->512) fused with attdot (asv/adv).
// Block = 128 threads = 4 nodes; thread owns 4 rows x 4 cols.
// ---------------------------------------------------------------------------
__global__ __launch_bounds__(128) void k_gath(const float* __restrict__ gw,
                                              const float* __restrict__ as,
                                              const float* __restrict__ ad) {
    __shared__ float sx[128];        // 4 rows x 32
    __shared__ float sp[128 * 8];    // per-thread partial dots
    int n0 = blockIdx.x * 4;
    int tid = threadIdx.x;
    int c4 = tid << 2;
    sx[tid] = g_x3[n0 * 32 + tid];
    __syncthreads();
    float4 acc[4];
#pragma unroll
    for (int r = 0; r < 4; r++) acc[r] = make_float4(0.f, 0.f, 0.f, 0.f);
#pragma unroll 4
    for (int k = 0; k < 32; k++) {
        float4 w = *(const float4*)(gw + k * 512 + c4);
#pragma unroll
        for (int r = 0; r < 4; r++) {
            float xv = sx[r * 32 + k];
            acc[r].x += xv * w.x; acc[r].y += xv * w.y;
            acc[r].z += xv * w.z; acc[r].w += xv * w.w;
        }
    }
    float4 av = *(const float4*)(as + c4);
    float4 dv = *(const float4*)(ad + c4);
#pragma unroll
    for (int r = 0; r < 4; r++) {
        *(float4*)(g_h + (n0 + r) * 512 + c4) = acc[r];
        sp[tid * 8 + r * 2 + 0] = acc[r].x * av.x + acc[r].y * av.y + acc[r].z * av.z + acc[r].w * av.w;
        sp[tid * 8 + r * 2 + 1] = acc[r].x * dv.x + acc[r].y * dv.y + acc[r].z * dv.z + acc[r].w * dv.w;
    }
    __syncthreads();
    int w = tid >> 5;      // warp id = row handled
    int lane = tid & 31;
    float s1 = 0.f, s2 = 0.f;
#pragma unroll
    for (int i = 0; i < 4; i++) {
        s1 += sp[(lane + 32 * i) * 8 + w * 2 + 0];
        s2 += sp[(lane + 32 * i) * 8 + w * 2 + 1];
    }
#pragma unroll
    for (int off = 16; off; off >>= 1) {
        s1 += __shfl_xor_sync(0xffffffffu, s1, off);
        s2 += __shfl_xor_sync(0xffffffffu, s2, off);
    }
    if (lane == 0) { g_asv[n0 + w] = s1; g_adv[n0 + w] = s2; }
}

// ---------------------------------------------------------------------------
// GAT softmax + aggregate fused. Block (128 threads) per node.
// ---------------------------------------------------------------------------
#define SM_CAP 2048
__global__ __launch_bounds__(128) void k_gatsm(const float* __restrict__ bias) {
    __shared__ float sal[SM_CAP];
    __shared__ float sred[128];
    int n = blockIdx.x;
    int tid = threadIdx.x;
    int beg = g_rowptr[n], end = g_rowptr[n + 1];
    int deg = end - beg;
    bool cached = deg <= SM_CAP;
    float advn = g_adv[n];
    float self_a = lrelu(g_asv[n] + advn);

    // pass 1: alphas + max
    float lmax = self_a;
    for (int i = tid; i < deg; i += 128) {
        float a = lrelu(g_asv[g_ssrc[beg + i]] + advn);
        if (cached) sal[i] = a;
        lmax = fmaxf(lmax, a);
    }
    sred[tid] = lmax;
    __syncthreads();
    if (tid < 64) sred[tid] = fmaxf(sred[tid], sred[tid + 64]);
    __syncthreads();
    if (tid < 32) {
        float v = fmaxf(sred[tid], sred[tid + 32]);
#pragma unroll
        for (int off = 16; off; off >>= 1)
            v = fmaxf(v, __shfl_xor_sync(0xffffffffu, v, off));
        if (tid == 0) sred[0] = v;
    }
    __syncthreads();
    float m = sred[0];
    __syncthreads();

    // pass 2: exp + sum (store exp in sal)
    float lsum = (tid == 0) ? __expf(self_a - m) : 0.f;
    for (int i = tid; i < deg; i += 128) {
        float a = cached ? sal[i] : lrelu(g_asv[g_ssrc[beg + i]] + advn);
        float ex = __expf(a - m);
        if (cached) sal[i] = ex;
        lsum += ex;
    }
    sred[tid] = lsum;
    __syncthreads();
    if (tid < 64) sred[tid] += sred[tid + 64];
    __syncthreads();
    if (tid < 32) {
        float v = sred[tid] + sred[tid + 32];
#pragma unroll
        for (int off = 16; off; off >>= 1)
            v += __shfl_xor_sync(0xffffffffu, v, off);
        if (tid == 0) sred[0] = v;
    }
    __syncthreads();
    float inv = 1.f / fmaxf(sred[0], 1e-16f);

    // pass 3: aggregate (thread owns 4 cols)
    int c4 = tid << 2;
    float4 hv = *(const float4*)(g_h + n * 512 + c4);
    float sc = __expf(self_a - m) * inv;
    float4 acc = make_float4(sc * hv.x, sc * hv.y, sc * hv.z, sc * hv.w);
    for (int e = 0; e < deg; e++) {
        float ex = cached ? sal[e]
                          : __expf(lrelu(g_asv[g_ssrc[beg + e]] + advn) - m);
        float c = ex * inv;
        int s = g_ssrc[beg + e];
        float4 v = *(const float4*)(g_h + s * 512 + c4);
        acc.x += c * v.x; acc.y += c * v.y; acc.z += c * v.z; acc.w += c * v.w;
    }
    float4 b = *(const float4*)(bias + c4);
    float4 o;
    o.x = fmaxf(acc.x + b.x, 0.f);
    o.y = fmaxf(acc.y + b.y, 0.f);
    o.z = fmaxf(acc.z + b.z, 0.f);
    o.w = fmaxf(acc.w + b.w, 0.f);
    *(float4*)(g_xb + n * 512 + c4) = o;
}

// ---------------------------------------------------------------------------
// A = x @ w1[0:512,:], B = x @ w1[512:,:]  — smem-tiled GEMM + packed f32x2.
// grid (NNP/64, 2), 256 threads. BM=64, BN=128, BK=32, per-thread 8x4.
// ---------------------------------------------------------------------------
__global__ __launch_bounds__(256) void k_ab(const float* __restrict__ w1) {
    __shared__ float xs[32][64];    // [k][m]
    __shared__ float ws[32][128];   // [k][n]
    int m0 = blockIdx.x * 64;
    const float* wb = w1 + blockIdx.y * (512 * 128);
    int tid = threadIdx.x;
    int col = (tid & 31) * 4;       // 0..124
    int row = (tid >> 5) * 8;       // 0..56
    ull accp[4][4];
#pragma unroll
    for (int i = 0; i < 4; i++)
#pragma unroll
        for (int j = 0; j < 4; j++) accp[i][j] = pk2(0.f, 0.f);

    for (int k0 = 0; k0 < 512; k0 += 32) {
#pragma unroll
        for (int i = 0; i < 2; i++) {
            int idx = tid + i * 256;
            int m = idx >> 3;
            int k4 = (idx & 7) * 4;
            float4 v = *(const float4*)(g_xb + (m0 + m) * 512 + k0 + k4);
            xs[k4 + 0][m] = v.x; xs[k4 + 1][m] = v.y;
            xs[k4 + 2][m] = v.z; xs[k4 + 3][m] = v.w;
        }
#pragma unroll
        for (int i = 0; i < 4; i++) {
            int idx = tid + i * 256;
            int kk = idx >> 5;
            int c4 = (idx & 31) * 4;
            *(float4*)&ws[kk][c4] = *(const float4*)(wb + (k0 + kk) * 128 + c4);
        }
        __syncthreads();
#pragma unroll
        for (int kk = 0; kk < 32; kk++) {
            float4 w = *(const float4*)&ws[kk][col];
            ull wd0 = pk2(w.x, w.x), wd1 = pk2(w.y, w.y);
            ull wd2 = pk2(w.z, w.z), wd3 = pk2(w.w, w.w);
#pragma unroll
            for (int r2 = 0; r2 < 4; r2++) {
                ull xp = *(const ull*)&xs[kk][row + 2 * r2];
                fma2(accp[r2][0], xp, wd0);
                fma2(accp[r2][1], xp, wd1);
                fma2(accp[r2][2], xp, wd2);
                fma2(accp[r2][3], xp, wd3);
            }
        }
        __syncthreads();
    }
    float* ob = blockIdx.y ? g_B : g_A;
#pragma unroll
    for (int r2 = 0; r2 < 4; r2++) {
        float4 vlo, vhi;
        upk2(vlo.x, vhi.x, accp[r2][0]);
        upk2(vlo.y, vhi.y, accp[r2][1]);
        upk2(vlo.z, vhi.z, accp[r2][2]);
        upk2(vlo.w, vhi.w, accp[r2][3]);
        *(float4*)(ob + (m0 + row + 2 * r2 + 0) * 128 + col) = vlo;
        *(float4*)(ob + (m0 + row + 2 * r2 + 1) * 128 + col) = vhi;
    }
}

// ---------------------------------------------------------------------------
// Edge MLP: h = relu(A[src] + B[dst] + b1);  out = sigmoid(h . w2 + b2)
// One warp per edge; each lane owns 4 of 128 hidden dims.
// ---------------------------------------------------------------------------
__global__ void k_mlp(const int* __restrict__ src, const int* __restrict__ dst,
                      const float* __restrict__ b1, const float* __restrict__ w2,
                      const float* __restrict__ b2, float* __restrict__ out) {
    int warp = (blockIdx.x * blockDim.x + threadIdx.x) >> 5;
    int lane = threadIdx.x & 31;
    if (warp >= EE) return;
    int e = warp;
    int s = src[e], d = dst[e];
    float4 a  = ((const float4*)(g_A + s * 128))[lane];
    float4 b  = ((const float4*)(g_B + d * 128))[lane];
    float4 bb = ((const float4*)b1)[lane];
    float4 w  = ((const float4*)w2)[lane];
    float hx = fmaxf(a.x + b.x + bb.x, 0.f);
    float hy = fmaxf(a.y + b.y + bb.y, 0.f);
    float hz = fmaxf(a.z + b.z + bb.z, 0.f);
    float hw = fmaxf(a.w + b.w + bb.w, 0.f);
    float z = hx * w.x + hy * w.y + hz * w.z + hw * w.w;
#pragma unroll
    for (int off = 16; off; off >>= 1)
        z += __shfl_xor_sync(0xffffffffu, z, off);
    if (lane == 0) {
        z += __ldg(b2);
        out[e] = 1.f / (1.f + __expf(-z));
    }
}

// ---------------------------------------------------------------------------
// Launch — robust input binding by element count (edge_index: 2*EE ints,
// edge_type: EE ints; remaining 24 float inputs keep relative order).
// ---------------------------------------------------------------------------
extern "C" void kernel_launch(void* const* d_in, const int* in_sizes, int n_in,
                              void* d_out, int out_size) {
    int ei_idx = -1, et_idx = -1;
    for (int i = 0; i < n_in; i++) {
        if (in_sizes[i] == 2 * EE) ei_idx = i;
        else if (in_sizes[i] == EE) et_idx = i;
    }
    const float* rest[24];
    int k = 0;
    for (int i = 0; i < n_in && k < 24; i++) {
        if (i == ei_idx || i == et_idx) continue;
        rest[k++] = (const float*)d_in[i];
    }

    const int* edge_index = (const int*)d_in[ei_idx];
    const int* src = edge_index;
    const int* dst = edge_index + EE;
    const int* etype = (const int*)d_in[et_idx];

    const float* basis[4] = {rest[0], rest[4], rest[8],  rest[12]};
    const float* comp[4]  = {rest[1], rest[5], rest[9],  rest[13]};
    const float* root[4]  = {rest[2], rest[6], rest[10], rest[14]};
    const float* rbias[4] = {rest[3], rest[7], rest[11], rest[15]};
    const float* gat_w   = rest[16];
    const float* att_src = rest[17];
    const float* att_dst = rest[18];
    const float* gat_b   = rest[19];
    const float* w1 = rest[20];
    const float* b1 = rest[21];
    const float* w2 = rest[22];
    const float* b2 = rest[23];
    float* out = (float*)d_out;

    const int TB = 256;
    const int PREP = 2 * NN * 32 + 6144 + 12288 + 6144;
    k_prep<<<(PREP + TB - 1) / TB, TB>>>(basis[0], comp[0],
                                         basis[1], comp[1], root[1],
                                         basis[2], comp[2], root[2],
                                         basis[3], comp[3], root[3]);
    k_hist<<<(EE + TB - 1) / TB, TB>>>(dst);
    k_scan<<<1, 256>>>();
    k_scatter<<<(EE + TB - 1) / TB, TB>>>(src, dst, etype);

    // Layer 0 + HR1 -> g_HRa
    k_l0<<<(NN * 32 + TB - 1) / TB, TB>>>(root[0], rbias[0]);
    // agg1 + HR2 : g_HRa -> g_HRb
    k_agg64<192, 6><<<(NN * 32 + TB - 1) / TB, TB>>>(rbias[1], g_HRa, g_HRb, WC2_OFF);
    // agg2 + HR3 : g_HRb -> g_HRa (J=96)
    k_agg64<96, 3><<<(NN * 32 + TB - 1) / TB, TB>>>(rbias[2], g_HRb, g_HRa, WC3_OFF);
    // agg3 -> g_x3
    k_agg3<<<(NN * 32 + TB - 1) / TB, TB>>>(rbias[3]);

    // GAT
    k_gath<<<NN / 4, 128>>>(gat_w, att_src, att_dst);
    k_gatsm<<<NN, 128>>>(gat_b);

    // Edge MLP via per-node precomputation
    dim3 gab(NNP / 64, 2);
    k_ab<<<gab, 256>>>(w1);
    k_mlp<<<(EE * 32 + TB - 1) / TB, TB>>>(src, dst, b1, w2, b2, out);
}

// round 13
// speedup vs baseline: 2.6135x; 2.6135x over previous
#include <cuda_runtime.h>
#include <math.h>

// Problem constants (fixed by the reference)
#define NN 6000          // N_USERS + N_ITEMS
#define NNP 6016         // padded row count (multiple of 64) for tiled GEMM
#define EE 100000        // edges
#define NREL 2

// ---------------------------------------------------------------------------
// Device scratch (static device globals — zero-initialized, no runtime alloc)
// NOTE: these symbols are ONLY referenced inside device code. Passing them as
// host-side kernel arguments takes the HOST shadow address, which GB300 ATS
// silently serves over NVLink-C2C (1222 cyc, 200 GB/s) — the round-12 bug.
// ---------------------------------------------------------------------------
__device__ int   g_cnt[NN];
__device__ int   g_rowptr[NN + 1];
__device__ int   g_cursor[NN];
__device__ int   g_ssrc[EE];        // CSR (by dst): source node per slot
__device__ int   g_stype[EE];       // CSR: edge type per slot

__device__ float g_W0[2 * NN * 32]; // layer-0 relation weights W[r][n][o]
__device__ float g_HRa[NN * 192];   // HR ping
__device__ float g_HRb[NN * 192];   // HR pong
__device__ float g_x3[NN * 32];     // layer-3 output (GAT input)
__device__ float g_h[NN * 512];     // GAT h
__device__ float g_xb[NNP * 512];   // GAT output (padded rows stay 0)
__device__ float g_WcAll[6144 + 12288 + 6144]; // fused weights layers 1..3
__device__ float g_asv[NN];
__device__ float g_adv[NN];
__device__ float g_A[NNP * 128];    // x @ w1[0:512]
__device__ float g_B[NNP * 128];    // x @ w1[512:1024]

#define WC1_OFF 0
#define WC2_OFF 6144
#define WC3_OFF 18432

__device__ __forceinline__ float lrelu(float x) { return x > 0.f ? x : 0.2f * x; }

__device__ __forceinline__ float tanh_ap(float x) {
    float r;
    asm("tanh.approx.f32 %0, %1;" : "=f"(r) : "f"(x));
    return r;
}

typedef unsigned long long ull;
__device__ __forceinline__ ull pk2(float lo, float hi) {
    ull r; asm("mov.b64 %0, {%1, %2};" : "=l"(r) : "f"(lo), "f"(hi)); return r;
}
__device__ __forceinline__ void upk2(float& lo, float& hi, ull v) {
    asm("mov.b64 {%0, %1}, %2;" : "=f"(lo), "=f"(hi) : "l"(v));
}
__device__ __forceinline__ void fma2(ull& c, ull a, ull b) {
    asm("fma.rn.f32x2 %0, %1, %2, %0;" : "+l"(c) : "l"(a), "l"(b));
}

// ---------------------------------------------------------------------------
// CSR build. g_cnt starts zero (static init first run; k_scan re-zeroes it
// after consuming, keeping every subsequent replay correct).
// ---------------------------------------------------------------------------
__global__ void k_hist(const int* __restrict__ dst) {
    int e = blockIdx.x * blockDim.x + threadIdx.x;
    if (e < EE) atomicAdd(&g_cnt[dst[e]], 1);
}

__global__ void k_scan() {
    __shared__ int sp[256];
    int tid = threadIdx.x;
    const int CH = (NN + 255) / 256;   // 24
    int base = tid * CH;
    int s = 0;
    for (int i = 0; i < CH; i++) {
        int idx = base + i;
        if (idx < NN) s += g_cnt[idx];
    }
    sp[tid] = s;
    __syncthreads();
    for (int off = 1; off < 256; off <<= 1) {
        int v = 0;
        if (tid >= off) v = sp[tid - off];
        __syncthreads();
        sp[tid] += v;
        __syncthreads();
    }
    int run = sp[tid] - s;  // exclusive prefix for this chunk
    for (int i = 0; i < CH; i++) {
        int idx = base + i;
        if (idx < NN) {
            int c = g_cnt[idx];
            g_rowptr[idx] = run;
            g_cursor[idx] = run;
            g_cnt[idx] = 0;          // reset for next replay
            run += c;
        }
    }
    if (tid == 255) g_rowptr[NN] = sp[255];
}

__global__ void k_scatter(const int* __restrict__ src, const int* __restrict__ dst,
                          const int* __restrict__ et) {
    int e = blockIdx.x * blockDim.x + threadIdx.x;
    if (e < EE) {
        int p = atomicAdd(&g_cursor[dst[e]], 1);
        g_ssrc[p]  = src[e];
        g_stype[p] = et[e];
    }
}

// ---------------------------------------------------------------------------
// Prep: W0 for layer 0; fused Wcat for layers 1..3.
// ---------------------------------------------------------------------------
__device__ __forceinline__ float wcat_elem(const float* __restrict__ basis,
                                           const float* __restrict__ comp,
                                           const float* __restrict__ root,
                                           int IN, int OUT, int i) {
    int J = 3 * OUT;
    int k = i / J;
    int j = i - k * J;
    if (j < 2 * OUT) {
        int r = j / OUT;
        int o = j - r * OUT;
        float v = 0.f;
#pragma unroll
        for (int b = 0; b < 4; b++)
            v += comp[r * 4 + b] * basis[(b * IN + k) * OUT + o];
        return v;
    }
    return root[k * OUT + (j - 2 * OUT)];
}

__global__ void k_prep(const float* __restrict__ basis0, const float* __restrict__ comp0,
                       const float* __restrict__ basis1, const float* __restrict__ comp1,
                       const float* __restrict__ root1,
                       const float* __restrict__ basis2, const float* __restrict__ comp2,
                       const float* __restrict__ root2,
                       const float* __restrict__ basis3, const float* __restrict__ comp3,
                       const float* __restrict__ root3) {
    int i = blockIdx.x * blockDim.x + threadIdx.x;
    if (i < 2 * NN * 32) {
        int r   = i / (NN * 32);
        int rem = i - r * (NN * 32);
        int n   = rem >> 5;
        int o   = rem & 31;
        float v = 0.f;
#pragma unroll
        for (int b = 0; b < 4; b++)
            v += comp0[r * 4 + b] * basis0[(b * NN + n) * 32 + o];
        g_W0[i] = v;
        return;
    }
    int j = i - 2 * NN * 32;
    if (j < 6144) { g_WcAll[WC1_OFF + j] = wcat_elem(basis1, comp1, root1, 32, 64, j); return; }
    j -= 6144;
    if (j < 12288) { g_WcAll[WC2_OFF + j] = wcat_elem(basis2, comp2, root2, 64, 64, j); return; }
    j -= 12288;
    if (j < 6144) { g_WcAll[WC3_OFF + j] = wcat_elem(basis3, comp3, root3, 64, 32, j); }
}

// ---------------------------------------------------------------------------
// Layer 0 (x = I) fused with HR1 = x0 @ Wcat1. x0 never hits global memory.
// Warp per node; lane owns x0 col `lane`; HR1 cols via warp shuffles.
// ---------------------------------------------------------------------------
__global__ void k_l0(const float* __restrict__ root0, const float* __restrict__ rbias0) {
    int warp = (blockIdx.x * blockDim.x + threadIdx.x) >> 5;
    int lane = threadIdx.x & 31;
    if (warp >= NN) return;
    int n = warp;
    int beg = g_rowptr[n], end = g_rowptr[n + 1];
    float a0 = 0.f, a1 = 0.f;
    int c0 = 0, c1 = 0;
    for (int e = beg; e < end; e++) {
        int s = g_ssrc[e];
        int t = g_stype[e];
        float v = g_W0[(t * NN + s) * 32 + lane];
        if (t == 0) { a0 += v; c0++; } else { a1 += v; c1++; }
    }
    float x = tanh_ap(root0[n * 32 + lane] + rbias0[lane]
                    + a0 / fmaxf((float)c0, 1.f) + a1 / fmaxf((float)c1, 1.f));
    // HR1[n, 192] = x0[n,:] @ Wcat1  (6 cols per lane)
    float acc[6] = {0.f, 0.f, 0.f, 0.f, 0.f, 0.f};
    const float* W = g_WcAll + WC1_OFF;
#pragma unroll 4
    for (int k = 0; k < 32; k++) {
        float xk = __shfl_sync(0xffffffffu, x, k);
        const float* wr = W + k * 192;
#pragma unroll
        for (int j = 0; j < 6; j++) acc[j] += xk * wr[lane + j * 32];
    }
#pragma unroll
    for (int j = 0; j < 6; j++) g_HRa[n * 192 + lane + j * 32] = acc[j];
}

// ---------------------------------------------------------------------------
// Fused RGCN agg (OUT=64) + next-layer HR (x stays in registers; shuffles).
// Warp per node: lane owns x cols {lane, lane+32}.
// IN_A selects HR ping/pong INSIDE device code (never pass device symbols
// from host — round-12 ATS bug).
// ---------------------------------------------------------------------------
template <int J2, int NCOL2, bool IN_A>
__global__ void k_agg64(const float* __restrict__ rbias, int wcoff) {
    const float* __restrict__ HRin  = IN_A ? g_HRa : g_HRb;
    float* __restrict__       HRout = IN_A ? g_HRb : g_HRa;
    int warp = (blockIdx.x * blockDim.x + threadIdx.x) >> 5;
    int lane = threadIdx.x & 31;
    if (warp >= NN) return;
    int n = warp;
    int beg = g_rowptr[n], end = g_rowptr[n + 1];
    float a0[2] = {0.f, 0.f}, a1[2] = {0.f, 0.f};
    int c0 = 0, c1 = 0;
    for (int e = beg; e < end; e++) {
        int s = g_ssrc[e];
        int t = g_stype[e];
        const float* hrow = HRin + s * 192 + t * 64;
        if (t == 0) {
            c0++; a0[0] += hrow[lane]; a0[1] += hrow[lane + 32];
        } else {
            c1++; a1[0] += hrow[lane]; a1[1] += hrow[lane + 32];
        }
    }
    float i0 = 1.f / fmaxf((float)c0, 1.f);
    float i1 = 1.f / fmaxf((float)c1, 1.f);
    float xlo = tanh_ap(HRin[n * 192 + 128 + lane]      + rbias[lane]      + a0[0] * i0 + a1[0] * i1);
    float xhi = tanh_ap(HRin[n * 192 + 128 + lane + 32] + rbias[lane + 32] + a0[1] * i0 + a1[1] * i1);
    // HRnext[n, J2] = x[n,:64] @ Wnext
    float acc[NCOL2];
#pragma unroll
    for (int j = 0; j < NCOL2; j++) acc[j] = 0.f;
    const float* W = g_WcAll + wcoff;
#pragma unroll 4
    for (int k = 0; k < 64; k++) {
        float xk = (k < 32) ? __shfl_sync(0xffffffffu, xlo, k)
                            : __shfl_sync(0xffffffffu, xhi, k - 32);
        const float* wr = W + k * J2;
#pragma unroll
        for (int j = 0; j < NCOL2; j++) acc[j] += xk * wr[lane + j * 32];
    }
#pragma unroll
    for (int j = 0; j < NCOL2; j++) HRout[n * J2 + lane + j * 32] = acc[j];
}

// Layer-3 agg (OUT=32): reads g_HRa (J=96), writes g_x3 for the GAT stage.
__global__ void k_agg3(const float* __restrict__ rbias) {
    int warp = (blockIdx.x * blockDim.x + threadIdx.x) >> 5;
    int lane = threadIdx.x & 31;
    if (warp >= NN) return;
    int n = warp;
    int beg = g_rowptr[n], end = g_rowptr[n + 1];
    float a0 = 0.f, a1 = 0.f;
    int c0 = 0, c1 = 0;
    for (int e = beg; e < end; e++) {
        int s = g_ssrc[e];
        int t = g_stype[e];
        float v = g_HRa[s * 96 + t * 32 + lane];
        if (t == 0) { a0 += v; c0++; } else { a1 += v; c1++; }
    }
    float o = g_HRa[n * 96 + 64 + lane] + rbias[lane]
            + a0 / fmaxf((float)c0, 1.f) + a1 / fmaxf((float)c1, 1.f);
    g_x3[n * 32 + lane] = tanh_ap(o);
}

// ---------------------------------------------------------------------------
// GAT h = x3 @ gat_w (32->512) fused with attdot (asv/adv).
// Block = 128 threads = 4 nodes; thread owns 4 rows x 4 cols.
// ---------------------------------------------------------------------------
__global__ __launch_bounds__(128) void k_gath(const float* __restrict__ gw,
                                              const float* __restrict__ as,
                                              const float* __restrict__ ad) {
    __shared__ float sx[128];        // 4 rows x 32
    __shared__ float sp[128 * 8];    // per-thread partial dots
    int n0 = blockIdx.x * 4;
    int tid = threadIdx.x;
    int c4 = tid << 2;
    sx[tid] = g_x3[n0 * 32 + tid];
    __syncthreads();
    float4 acc[4];
#pragma unroll
    for (int r = 0; r < 4; r++) acc[r] = make_float4(0.f, 0.f, 0.f, 0.f);
#pragma unroll 4
    for (int k = 0; k < 32; k++) {
        float4 w = *(const float4*)(gw + k * 512 + c4);
#pragma unroll
        for (int r = 0; r < 4; r++) {
            float xv = sx[r * 32 + k];
            acc[r].x += xv * w.x; acc[r].y += xv * w.y;
            acc[r].z += xv * w.z; acc[r].w += xv * w.w;
        }
    }
    float4 av = *(const float4*)(as + c4);
    float4 dv = *(const float4*)(ad + c4);
#pragma unroll
    for (int r = 0; r < 4; r++) {
        *(float4*)(g_h + (n0 + r) * 512 + c4) = acc[r];
        sp[tid * 8 + r * 2 + 0] = acc[r].x * av.x + acc[r].y * av.y + acc[r].z * av.z + acc[r].w * av.w;
        sp[tid * 8 + r * 2 + 1] = acc[r].x * dv.x + acc[r].y * dv.y + acc[r].z * dv.z + acc[r].w * dv.w;
    }
    __syncthreads();
    int w = tid >> 5;      // warp id = row handled
    int lane = tid & 31;
    float s1 = 0.f, s2 = 0.f;
#pragma unroll
    for (int i = 0; i < 4; i++) {
        s1 += sp[(lane + 32 * i) * 8 + w * 2 + 0];
        s2 += sp[(lane + 32 * i) * 8 + w * 2 + 1];
    }
#pragma unroll
    for (int off = 16; off; off >>= 1) {
        s1 += __shfl_xor_sync(0xffffffffu, s1, off);
        s2 += __shfl_xor_sync(0xffffffffu, s2, off);
    }
    if (lane == 0) { g_asv[n0 + w] = s1; g_adv[n0 + w] = s2; }
}

// ---------------------------------------------------------------------------
// GAT softmax + aggregate fused. Block (128 threads) per node.
// ---------------------------------------------------------------------------
#define SM_CAP 2048
__global__ __launch_bounds__(128) void k_gatsm(const float* __restrict__ bias) {
    __shared__ float sal[SM_CAP];
    __shared__ float sred[128];
    int n = blockIdx.x;
    int tid = threadIdx.x;
    int beg = g_rowptr[n], end = g_rowptr[n + 1];
    int deg = end - beg;
    bool cached = deg <= SM_CAP;
    float advn = g_adv[n];
    float self_a = lrelu(g_asv[n] + advn);

    // pass 1: alphas + max
    float lmax = self_a;
    for (int i = tid; i < deg; i += 128) {
        float a = lrelu(g_asv[g_ssrc[beg + i]] + advn);
        if (cached) sal[i] = a;
        lmax = fmaxf(lmax, a);
    }
    sred[tid] = lmax;
    __syncthreads();
    if (tid < 64) sred[tid] = fmaxf(sred[tid], sred[tid + 64]);
    __syncthreads();
    if (tid < 32) {
        float v = fmaxf(sred[tid], sred[tid + 32]);
#pragma unroll
        for (int off = 16; off; off >>= 1)
            v = fmaxf(v, __shfl_xor_sync(0xffffffffu, v, off));
        if (tid == 0) sred[0] = v;
    }
    __syncthreads();
    float m = sred[0];
    __syncthreads();

    // pass 2: exp + sum (store exp in sal)
    float lsum = (tid == 0) ? __expf(self_a - m) : 0.f;
    for (int i = tid; i < deg; i += 128) {
        float a = cached ? sal[i] : lrelu(g_asv[g_ssrc[beg + i]] + advn);
        float ex = __expf(a - m);
        if (cached) sal[i] = ex;
        lsum += ex;
    }
    sred[tid] = lsum;
    __syncthreads();
    if (tid < 64) sred[tid] += sred[tid + 64];
    __syncthreads();
    if (tid < 32) {
        float v = sred[tid] + sred[tid + 32];
#pragma unroll
        for (int off = 16; off; off >>= 1)
            v += __shfl_xor_sync(0xffffffffu, v, off);
        if (tid == 0) sred[0] = v;
    }
    __syncthreads();
    float inv = 1.f / fmaxf(sred[0], 1e-16f);

    // pass 3: aggregate (thread owns 4 cols)
    int c4 = tid << 2;
    float4 hv = *(const float4*)(g_h + n * 512 + c4);
    float sc = __expf(self_a - m) * inv;
    float4 acc = make_float4(sc * hv.x, sc * hv.y, sc * hv.z, sc * hv.w);
    for (int e = 0; e < deg; e++) {
        float ex = cached ? sal[e]
                          : __expf(lrelu(g_asv[g_ssrc[beg + e]] + advn) - m);
        float c = ex * inv;
        int s = g_ssrc[beg + e];
        float4 v = *(const float4*)(g_h + s * 512 + c4);
        acc.x += c * v.x; acc.y += c * v.y; acc.z += c * v.z; acc.w += c * v.w;
    }
    float4 b = *(const float4*)(bias + c4);
    float4 o;
    o.x = fmaxf(acc.x + b.x, 0.f);
    o.y = fmaxf(acc.y + b.y, 0.f);
    o.z = fmaxf(acc.z + b.z, 0.f);
    o.w = fmaxf(acc.w + b.w, 0.f);
    *(float4*)(g_xb + n * 512 + c4) = o;
}

// ---------------------------------------------------------------------------
// A = x @ w1[0:512,:], B = x @ w1[512:,:]  — smem-tiled GEMM + packed f32x2.
// grid (NNP/64, 2), 256 threads. BM=64, BN=128, BK=32, per-thread 8x4.
// ---------------------------------------------------------------------------
__global__ __launch_bounds__(256) void k_ab(const float* __restrict__ w1) {
    __shared__ float xs[32][64];    // [k][m]
    __shared__ float ws[32][128];   // [k][n]
    int m0 = blockIdx.x * 64;
    const float* wb = w1 + blockIdx.y * (512 * 128);
    int tid = threadIdx.x;
    int col = (tid & 31) * 4;       // 0..124
    int row = (tid >> 5) * 8;       // 0..56
    ull accp[4][4];
#pragma unroll
    for (int i = 0; i < 4; i++)
#pragma unroll
        for (int j = 0; j < 4; j++) accp[i][j] = pk2(0.f, 0.f);

    for (int k0 = 0; k0 < 512; k0 += 32) {
#pragma unroll
        for (int i = 0; i < 2; i++) {
            int idx = tid + i * 256;
            int m = idx >> 3;
            int k4 = (idx & 7) * 4;
            float4 v = *(const float4*)(g_xb + (m0 + m) * 512 + k0 + k4);
            xs[k4 + 0][m] = v.x; xs[k4 + 1][m] = v.y;
            xs[k4 + 2][m] = v.z; xs[k4 + 3][m] = v.w;
        }
#pragma unroll
        for (int i = 0; i < 4; i++) {
            int idx = tid + i * 256;
            int kk = idx >> 5;
            int c4 = (idx & 31) * 4;
            *(float4*)&ws[kk][c4] = *(const float4*)(wb + (k0 + kk) * 128 + c4);
        }
        __syncthreads();
#pragma unroll
        for (int kk = 0; kk < 32; kk++) {
            float4 w = *(const float4*)&ws[kk][col];
            ull wd0 = pk2(w.x, w.x), wd1 = pk2(w.y, w.y);
            ull wd2 = pk2(w.z, w.z), wd3 = pk2(w.w, w.w);
#pragma unroll
            for (int r2 = 0; r2 < 4; r2++) {
                ull xp = *(const ull*)&xs[kk][row + 2 * r2];
                fma2(accp[r2][0], xp, wd0);
                fma2(accp[r2][1], xp, wd1);
                fma2(accp[r2][2], xp, wd2);
                fma2(accp[r2][3], xp, wd3);
            }
        }
        __syncthreads();
    }
    float* ob = blockIdx.y ? g_B : g_A;
#pragma unroll
    for (int r2 = 0; r2 < 4; r2++) {
        float4 vlo, vhi;
        upk2(vlo.x, vhi.x, accp[r2][0]);
        upk2(vlo.y, vhi.y, accp[r2][1]);
        upk2(vlo.z, vhi.z, accp[r2][2]);
        upk2(vlo.w, vhi.w, accp[r2][3]);
        *(float4*)(ob + (m0 + row + 2 * r2 + 0) * 128 + col) = vlo;
        *(float4*)(ob + (m0 + row + 2 * r2 + 1) * 128 + col) = vhi;
    }
}

// ---------------------------------------------------------------------------
// Edge MLP: h = relu(A[src] + B[dst] + b1);  out = sigmoid(h . w2 + b2)
// One warp per edge; each lane owns 4 of 128 hidden dims.
// ---------------------------------------------------------------------------
__global__ void k_mlp(const int* __restrict__ src, const int* __restrict__ dst,
                      const float* __restrict__ b1, const float* __restrict__ w2,
                      const float* __restrict__ b2, float* __restrict__ out) {
    int warp = (blockIdx.x * blockDim.x + threadIdx.x) >> 5;
    int lane = threadIdx.x & 31;
    if (warp >= EE) return;
    int e = warp;
    int s = src[e], d = dst[e];
    float4 a  = ((const float4*)(g_A + s * 128))[lane];
    float4 b  = ((const float4*)(g_B + d * 128))[lane];
    float4 bb = ((const float4*)b1)[lane];
    float4 w  = ((const float4*)w2)[lane];
    float hx = fmaxf(a.x + b.x + bb.x, 0.f);
    float hy = fmaxf(a.y + b.y + bb.y, 0.f);
    float hz = fmaxf(a.z + b.z + bb.z, 0.f);
    float hw = fmaxf(a.w + b.w + bb.w, 0.f);
    float z = hx * w.x + hy * w.y + hz * w.z + hw * w.w;
#pragma unroll
    for (int off = 16; off; off >>= 1)
        z += __shfl_xor_sync(0xffffffffu, z, off);
    if (lane == 0) {
        z += __ldg(b2);
        out[e] = 1.f / (1.f + __expf(-z));
    }
}

// ---------------------------------------------------------------------------
// Launch — robust input binding by element count (edge_index: 2*EE ints,
// edge_type: EE ints; remaining 24 float inputs keep relative order).
// All kernel arguments derive from d_in/d_out only — never device symbols.
// ---------------------------------------------------------------------------
extern "C" void kernel_launch(void* const* d_in, const int* in_sizes, int n_in,
                              void* d_out, int out_size) {
    int ei_idx = -1, et_idx = -1;
    for (int i = 0; i < n_in; i++) {
        if (in_sizes[i] == 2 * EE) ei_idx = i;
        else if (in_sizes[i] == EE) et_idx = i;
    }
    const float* rest[24];
    int k = 0;
    for (int i = 0; i < n_in && k < 24; i++) {
        if (i == ei_idx || i == et_idx) continue;
        rest[k++] = (const float*)d_in[i];
    }

    const int* edge_index = (const int*)d_in[ei_idx];
    const int* src = edge_index;
    const int* dst = edge_index + EE;
    const int* etype = (const int*)d_in[et_idx];

    const float* basis[4] = {rest[0], rest[4], rest[8],  rest[12]};
    const float* comp[4]  = {rest[1], rest[5], rest[9],  rest[13]};
    const float* root[4]  = {rest[2], rest[6], rest[10], rest[14]};
    const float* rbias[4] = {rest[3], rest[7], rest[11], rest[15]};
    const float* gat_w   = rest[16];
    const float* att_src = rest[17];
    const float* att_dst = rest[18];
    const float* gat_b   = rest[19];
    const float* w1 = rest[20];
    const float* b1 = rest[21];
    const float* w2 = rest[22];
    const float* b2 = rest[23];
    float* out = (float*)d_out;

    const int TB = 256;
    const int PREP = 2 * NN * 32 + 6144 + 12288 + 6144;
    k_prep<<<(PREP + TB - 1) / TB, TB>>>(basis[0], comp[0],
                                         basis[1], comp[1], root[1],
                                         basis[2], comp[2], root[2],
                                         basis[3], comp[3], root[3]);
    k_hist<<<(EE + TB - 1) / TB, TB>>>(dst);
    k_scan<<<1, 256>>>();
    k_scatter<<<(EE + TB - 1) / TB, TB>>>(src, dst, etype);

    // Layer 0 + HR1 -> g_HRa
    k_l0<<<(NN * 32 + TB - 1) / TB, TB>>>(root[0], rbias[0]);
    // agg1 + HR2 : g_HRa -> g_HRb  (buffer choice via template, in device code)
    k_agg64<192, 6, true><<<(NN * 32 + TB - 1) / TB, TB>>>(rbias[1], WC2_OFF);
    // agg2 + HR3 : g_HRb -> g_HRa (J=96)
    k_agg64<96, 3, false><<<(NN * 32 + TB - 1) / TB, TB>>>(rbias[2], WC3_OFF);
    // agg3 -> g_x3
    k_agg3<<<(NN * 32 + TB - 1) / TB, TB>>>(rbias[3]);

    // GAT
    k_gath<<<NN / 4, 128>>>(gat_w, att_src, att_dst);
    k_gatsm<<<NN, 128>>>(gat_b);

    // Edge MLP via per-node precomputation
    dim3 gab(NNP / 64, 2);
    k_ab<<<gab, 256>>>(w1);
    k_mlp<<<(EE * 32 + TB - 1) / TB, TB>>>(src, dst, b1, w2, b2, out);
}

// round 14
// speedup vs baseline: 2.6850x; 1.0274x over previous
#include <cuda_runtime.h>
#include <math.h>

// Problem constants (fixed by the reference)
#define NN 6000          // N_USERS + N_ITEMS
#define NNP 6016         // padded row count (multiple of 64) for tiled GEMM
#define EE 100000        // edges
#define NREL 2

// ---------------------------------------------------------------------------
// Device scratch (static device globals — zero-initialized, no runtime alloc)
// NOTE: symbols only referenced inside device code (host-side use would take
// the host shadow address -> silent ATS/C2C traffic, the round-12 bug).
// ---------------------------------------------------------------------------
__device__ int   g_cnt[NN];
__device__ int   g_rowptr[NN + 1];
__device__ int   g_cursor[NN];
__device__ int   g_ssrc[EE];        // CSR (by dst): source node per slot
__device__ int   g_sdst[EE];        // CSR: dst node per slot
__device__ int   g_seid[EE];        // CSR: original edge id per slot
__device__ int   g_stype[EE];       // CSR: edge type per slot

__device__ float g_W0[2 * NN * 32]; // layer-0 relation weights W[r][n][o]
__device__ float g_HRa[NN * 192];   // HR ping
__device__ float g_HRb[NN * 192];   // HR pong
__device__ float g_h[NN * 512];     // GAT h
__device__ float g_xb[NNP * 512];   // GAT output (padded rows stay 0)
__device__ float g_WcAll[6144 + 12288 + 6144]; // fused weights layers 1..3
__device__ float g_asv[NN];
__device__ float g_adv[NN];
__device__ float g_A[NNP * 128];    // x @ w1[0:512]
__device__ float g_B[NNP * 128];    // x @ w1[512:1024]

#define WC1_OFF 0
#define WC2_OFF 6144
#define WC3_OFF 18432

__device__ __forceinline__ float lrelu(float x) { return x > 0.f ? x : 0.2f * x; }

__device__ __forceinline__ float tanh_ap(float x) {
    float r;
    asm("tanh.approx.f32 %0, %1;" : "=f"(r) : "f"(x));
    return r;
}

typedef unsigned long long ull;
__device__ __forceinline__ ull pk2(float lo, float hi) {
    ull r; asm("mov.b64 %0, {%1, %2};" : "=l"(r) : "f"(lo), "f"(hi)); return r;
}
__device__ __forceinline__ void upk2(float& lo, float& hi, ull v) {
    asm("mov.b64 {%0, %1}, %2;" : "=f"(lo), "=f"(hi) : "l"(v));
}
__device__ __forceinline__ void fma2(ull& c, ull a, ull b) {
    asm("fma.rn.f32x2 %0, %1, %2, %0;" : "+l"(c) : "l"(a), "l"(b));
}

// ---------------------------------------------------------------------------
// Prep (W0, Wcat1..3) + histogram, merged: all ranges depend only on inputs.
// g_cnt starts zero (static init; k_scan re-zeroes after consuming).
// ---------------------------------------------------------------------------
__device__ __forceinline__ float wcat_elem(const float* __restrict__ basis,
                                           const float* __restrict__ comp,
                                           const float* __restrict__ root,
                                           int IN, int OUT, int i) {
    int J = 3 * OUT;
    int k = i / J;
    int j = i - k * J;
    if (j < 2 * OUT) {
        int r = j / OUT;
        int o = j - r * OUT;
        float v = 0.f;
#pragma unroll
        for (int b = 0; b < 4; b++)
            v += comp[r * 4 + b] * basis[(b * IN + k) * OUT + o];
        return v;
    }
    return root[k * OUT + (j - 2 * OUT)];
}

__global__ void k_prep(const float* __restrict__ basis0, const float* __restrict__ comp0,
                       const float* __restrict__ basis1, const float* __restrict__ comp1,
                       const float* __restrict__ root1,
                       const float* __restrict__ basis2, const float* __restrict__ comp2,
                       const float* __restrict__ root2,
                       const float* __restrict__ basis3, const float* __restrict__ comp3,
                       const float* __restrict__ root3,
                       const int* __restrict__ dst) {
    int i = blockIdx.x * blockDim.x + threadIdx.x;
    if (i < 2 * NN * 32) {
        int r   = i / (NN * 32);
        int rem = i - r * (NN * 32);
        int n   = rem >> 5;
        int o   = rem & 31;
        float v = 0.f;
#pragma unroll
        for (int b = 0; b < 4; b++)
            v += comp0[r * 4 + b] * basis0[(b * NN + n) * 32 + o];
        g_W0[i] = v;
        return;
    }
    int j = i - 2 * NN * 32;
    if (j < 6144) { g_WcAll[WC1_OFF + j] = wcat_elem(basis1, comp1, root1, 32, 64, j); return; }
    j -= 6144;
    if (j < 12288) { g_WcAll[WC2_OFF + j] = wcat_elem(basis2, comp2, root2, 64, 64, j); return; }
    j -= 12288;
    if (j < 6144) { g_WcAll[WC3_OFF + j] = wcat_elem(basis3, comp3, root3, 64, 32, j); return; }
    j -= 6144;
    if (j < EE) atomicAdd(&g_cnt[dst[j]], 1);
}

__global__ void k_scan() {
    __shared__ int sp[256];
    int tid = threadIdx.x;
    const int CH = (NN + 255) / 256;   // 24
    int base = tid * CH;
    int s = 0;
    for (int i = 0; i < CH; i++) {
        int idx = base + i;
        if (idx < NN) s += g_cnt[idx];
    }
    sp[tid] = s;
    __syncthreads();
    for (int off = 1; off < 256; off <<= 1) {
        int v = 0;
        if (tid >= off) v = sp[tid - off];
        __syncthreads();
        sp[tid] += v;
        __syncthreads();
    }
    int run = sp[tid] - s;  // exclusive prefix for this chunk
    for (int i = 0; i < CH; i++) {
        int idx = base + i;
        if (idx < NN) {
            int c = g_cnt[idx];
            g_rowptr[idx] = run;
            g_cursor[idx] = run;
            g_cnt[idx] = 0;          // reset for next replay
            run += c;
        }
    }
    if (tid == 255) g_rowptr[NN] = sp[255];
}

__global__ void k_scatter(const int* __restrict__ src, const int* __restrict__ dst,
                          const int* __restrict__ et) {
    int e = blockIdx.x * blockDim.x + threadIdx.x;
    if (e < EE) {
        int d = dst[e];
        int p = atomicAdd(&g_cursor[d], 1);
        g_ssrc[p]  = src[e];
        g_sdst[p]  = d;
        g_seid[p]  = e;
        g_stype[p] = et[e];
    }
}

// ---------------------------------------------------------------------------
// Layer 0 (x = I) fused with HR1 = x0 @ Wcat1. x0 never hits global memory.
// Warp per node; lane owns x0 col `lane`; HR1 cols via warp shuffles.
// ---------------------------------------------------------------------------
__global__ void k_l0(const float* __restrict__ root0, const float* __restrict__ rbias0) {
    int warp = (blockIdx.x * blockDim.x + threadIdx.x) >> 5;
    int lane = threadIdx.x & 31;
    if (warp >= NN) return;
    int n = warp;
    int beg = g_rowptr[n], end = g_rowptr[n + 1];
    float a0 = 0.f, a1 = 0.f;
    int c0 = 0, c1 = 0;
    for (int e = beg; e < end; e++) {
        int s = g_ssrc[e];
        int t = g_stype[e];
        float v = g_W0[(t * NN + s) * 32 + lane];
        if (t == 0) { a0 += v; c0++; } else { a1 += v; c1++; }
    }
    float x = tanh_ap(root0[n * 32 + lane] + rbias0[lane]
                    + a0 / fmaxf((float)c0, 1.f) + a1 / fmaxf((float)c1, 1.f));
    float acc[6] = {0.f, 0.f, 0.f, 0.f, 0.f, 0.f};
    const float* W = g_WcAll + WC1_OFF;
#pragma unroll 4
    for (int k = 0; k < 32; k++) {
        float xk = __shfl_sync(0xffffffffu, x, k);
        const float* wr = W + k * 192;
#pragma unroll
        for (int j = 0; j < 6; j++) acc[j] += xk * wr[lane + j * 32];
    }
#pragma unroll
    for (int j = 0; j < 6; j++) g_HRa[n * 192 + lane + j * 32] = acc[j];
}

// ---------------------------------------------------------------------------
// Fused RGCN agg (OUT=64) + next-layer HR (x stays in registers; shuffles).
// IN_A selects HR ping/pong INSIDE device code.
// ---------------------------------------------------------------------------
template <int J2, int NCOL2, bool IN_A>
__global__ void k_agg64(const float* __restrict__ rbias, int wcoff) {
    const float* __restrict__ HRin  = IN_A ? g_HRa : g_HRb;
    float* __restrict__       HRout = IN_A ? g_HRb : g_HRa;
    int warp = (blockIdx.x * blockDim.x + threadIdx.x) >> 5;
    int lane = threadIdx.x & 31;
    if (warp >= NN) return;
    int n = warp;
    int beg = g_rowptr[n], end = g_rowptr[n + 1];
    float a0[2] = {0.f, 0.f}, a1[2] = {0.f, 0.f};
    int c0 = 0, c1 = 0;
    for (int e = beg; e < end; e++) {
        int s = g_ssrc[e];
        int t = g_stype[e];
        const float* hrow = HRin + s * 192 + t * 64;
        if (t == 0) {
            c0++; a0[0] += hrow[lane]; a0[1] += hrow[lane + 32];
        } else {
            c1++; a1[0] += hrow[lane]; a1[1] += hrow[lane + 32];
        }
    }
    float i0 = 1.f / fmaxf((float)c0, 1.f);
    float i1 = 1.f / fmaxf((float)c1, 1.f);
    float xlo = tanh_ap(HRin[n * 192 + 128 + lane]      + rbias[lane]      + a0[0] * i0 + a1[0] * i1);
    float xhi = tanh_ap(HRin[n * 192 + 128 + lane + 32] + rbias[lane + 32] + a0[1] * i0 + a1[1] * i1);
    float acc[NCOL2];
#pragma unroll
    for (int j = 0; j < NCOL2; j++) acc[j] = 0.f;
    const float* W = g_WcAll + wcoff;
#pragma unroll 4
    for (int k = 0; k < 64; k++) {
        float xk = (k < 32) ? __shfl_sync(0xffffffffu, xlo, k)
                            : __shfl_sync(0xffffffffu, xhi, k - 32);
        const float* wr = W + k * J2;
#pragma unroll
        for (int j = 0; j < NCOL2; j++) acc[j] += xk * wr[lane + j * 32];
    }
#pragma unroll
    for (int j = 0; j < NCOL2; j++) HRout[n * J2 + lane + j * 32] = acc[j];
}

// ---------------------------------------------------------------------------
// Fused: layer-3 agg (reads g_HRa J=96) + GAT h-GEMM (32->512) + attdot.
// Block = 128 threads = 4 warps = 4 nodes. Warp computes its node's x3 into
// smem; then threads compute h (4 rows x 4 cols), asv/adv reductions.
// ---------------------------------------------------------------------------
__global__ __launch_bounds__(128) void k_gath3(const float* __restrict__ rbias,
                                               const float* __restrict__ gw,
                                               const float* __restrict__ as,
                                               const float* __restrict__ ad) {
    __shared__ float sx[128];        // 4 rows x 32  (x3)
    __shared__ float sp[128 * 8];    // per-thread partial dots
    int n0 = blockIdx.x * 4;
    int tid = threadIdx.x;
    int w = tid >> 5;
    int lane = tid & 31;

    // --- agg3 for node n0+w (warp-parallel over its edges) ---
    {
        int n = n0 + w;
        int beg = g_rowptr[n], end = g_rowptr[n + 1];
        float a0 = 0.f, a1 = 0.f;
        int c0 = 0, c1 = 0;
        for (int e = beg; e < end; e++) {
            int s = g_ssrc[e];
            int t = g_stype[e];
            float v = g_HRa[s * 96 + t * 32 + lane];
            if (t == 0) { a0 += v; c0++; } else { a1 += v; c1++; }
        }
        float o = g_HRa[n * 96 + 64 + lane] + rbias[lane]
                + a0 / fmaxf((float)c0, 1.f) + a1 / fmaxf((float)c1, 1.f);
        sx[w * 32 + lane] = tanh_ap(o);
    }
    __syncthreads();

    // --- h = x3 @ gw, 4 rows per thread-column group ---
    int c4 = tid << 2;
    float4 acc[4];
#pragma unroll
    for (int r = 0; r < 4; r++) acc[r] = make_float4(0.f, 0.f, 0.f, 0.f);
#pragma unroll 4
    for (int k = 0; k < 32; k++) {
        float4 wv = *(const float4*)(gw + k * 512 + c4);
#pragma unroll
        for (int r = 0; r < 4; r++) {
            float xv = sx[r * 32 + k];
            acc[r].x += xv * wv.x; acc[r].y += xv * wv.y;
            acc[r].z += xv * wv.z; acc[r].w += xv * wv.w;
        }
    }
    float4 av = *(const float4*)(as + c4);
    float4 dv = *(const float4*)(ad + c4);
#pragma unroll
    for (int r = 0; r < 4; r++) {
        *(float4*)(g_h + (n0 + r) * 512 + c4) = acc[r];
        sp[tid * 8 + r * 2 + 0] = acc[r].x * av.x + acc[r].y * av.y + acc[r].z * av.z + acc[r].w * av.w;
        sp[tid * 8 + r * 2 + 1] = acc[r].x * dv.x + acc[r].y * dv.y + acc[r].z * dv.z + acc[r].w * dv.w;
    }
    __syncthreads();
    float s1 = 0.f, s2 = 0.f;
#pragma unroll
    for (int i = 0; i < 4; i++) {
        s1 += sp[(lane + 32 * i) * 8 + w * 2 + 0];
        s2 += sp[(lane + 32 * i) * 8 + w * 2 + 1];
    }
#pragma unroll
    for (int off = 16; off; off >>= 1) {
        s1 += __shfl_xor_sync(0xffffffffu, s1, off);
        s2 += __shfl_xor_sync(0xffffffffu, s2, off);
    }
    if (lane == 0) { g_asv[n0 + w] = s1; g_adv[n0 + w] = s2; }
}

// ---------------------------------------------------------------------------
// GAT softmax + aggregate fused, NO max pass (alphas bounded; exp(a)/sum is
// math-identical to the max-subtracted form). Block (128 threads) per node.
// ---------------------------------------------------------------------------
#define SM_CAP 2048
__global__ __launch_bounds__(128) void k_gatsm(const float* __restrict__ bias) {
    __shared__ float sal[SM_CAP];
    __shared__ float sred[128];
    int n = blockIdx.x;
    int tid = threadIdx.x;
    int beg = g_rowptr[n], end = g_rowptr[n + 1];
    int deg = end - beg;
    bool cached = deg <= SM_CAP;
    float advn = g_adv[n];
    float self_ex = __expf(lrelu(g_asv[n] + advn));

    // pass 1: exp + sum
    float lsum = (tid == 0) ? self_ex : 0.f;
    for (int i = tid; i < deg; i += 128) {
        float ex = __expf(lrelu(g_asv[g_ssrc[beg + i]] + advn));
        if (cached) sal[i] = ex;
        lsum += ex;
    }
    sred[tid] = lsum;
    __syncthreads();
    if (tid < 64) sred[tid] += sred[tid + 64];
    __syncthreads();
    if (tid < 32) {
        float v = sred[tid] + sred[tid + 32];
#pragma unroll
        for (int off = 16; off; off >>= 1)
            v += __shfl_xor_sync(0xffffffffu, v, off);
        if (tid == 0) sred[0] = v;
    }
    __syncthreads();
    float inv = 1.f / fmaxf(sred[0], 1e-16f);

    // pass 2: aggregate (thread owns 4 cols)
    int c4 = tid << 2;
    float4 hv = *(const float4*)(g_h + n * 512 + c4);
    float sc = self_ex * inv;
    float4 acc = make_float4(sc * hv.x, sc * hv.y, sc * hv.z, sc * hv.w);
    for (int e = 0; e < deg; e++) {
        float ex = cached ? sal[e]
                          : __expf(lrelu(g_asv[g_ssrc[beg + e]] + advn));
        float c = ex * inv;
        int s = g_ssrc[beg + e];
        float4 v = *(const float4*)(g_h + s * 512 + c4);
        acc.x += c * v.x; acc.y += c * v.y; acc.z += c * v.z; acc.w += c * v.w;
    }
    float4 b = *(const float4*)(bias + c4);
    float4 o;
    o.x = fmaxf(acc.x + b.x, 0.f);
    o.y = fmaxf(acc.y + b.y, 0.f);
    o.z = fmaxf(acc.z + b.z, 0.f);
    o.w = fmaxf(acc.w + b.w, 0.f);
    *(float4*)(g_xb + n * 512 + c4) = o;
}

// ---------------------------------------------------------------------------
// A = x @ w1[0:512,:], B = x @ w1[512:,:]  — smem-tiled GEMM + packed f32x2.
// grid (NNP/64, 2), 256 threads. BM=64, BN=128, BK=32, per-thread 8x4.
// ---------------------------------------------------------------------------
__global__ __launch_bounds__(256) void k_ab(const float* __restrict__ w1) {
    __shared__ float xs[32][64];    // [k][m]
    __shared__ float ws[32][128];   // [k][n]
    int m0 = blockIdx.x * 64;
    const float* wb = w1 + blockIdx.y * (512 * 128);
    int tid = threadIdx.x;
    int col = (tid & 31) * 4;       // 0..124
    int row = (tid >> 5) * 8;       // 0..56
    ull accp[4][4];
#pragma unroll
    for (int i = 0; i < 4; i++)
#pragma unroll
        for (int j = 0; j < 4; j++) accp[i][j] = pk2(0.f, 0.f);

    for (int k0 = 0; k0 < 512; k0 += 32) {
#pragma unroll
        for (int i = 0; i < 2; i++) {
            int idx = tid + i * 256;
            int m = idx >> 3;
            int k4 = (idx & 7) * 4;
            float4 v = *(const float4*)(g_xb + (m0 + m) * 512 + k0 + k4);
            xs[k4 + 0][m] = v.x; xs[k4 + 1][m] = v.y;
            xs[k4 + 2][m] = v.z; xs[k4 + 3][m] = v.w;
        }
#pragma unroll
        for (int i = 0; i < 4; i++) {
            int idx = tid + i * 256;
            int kk = idx >> 5;
            int c4 = (idx & 31) * 4;
            *(float4*)&ws[kk][c4] = *(const float4*)(wb + (k0 + kk) * 128 + c4);
        }
        __syncthreads();
#pragma unroll
        for (int kk = 0; kk < 32; kk++) {
            float4 w = *(const float4*)&ws[kk][col];
            ull wd0 = pk2(w.x, w.x), wd1 = pk2(w.y, w.y);
            ull wd2 = pk2(w.z, w.z), wd3 = pk2(w.w, w.w);
#pragma unroll
            for (int r2 = 0; r2 < 4; r2++) {
                ull xp = *(const ull*)&xs[kk][row + 2 * r2];
                fma2(accp[r2][0], xp, wd0);
                fma2(accp[r2][1], xp, wd1);
                fma2(accp[r2][2], xp, wd2);
                fma2(accp[r2][3], xp, wd3);
            }
        }
        __syncthreads();
    }
    float* ob = blockIdx.y ? g_B : g_A;
#pragma unroll
    for (int r2 = 0; r2 < 4; r2++) {
        float4 vlo, vhi;
        upk2(vlo.x, vhi.x, accp[r2][0]);
        upk2(vlo.y, vhi.y, accp[r2][1]);
        upk2(vlo.z, vhi.z, accp[r2][2]);
        upk2(vlo.w, vhi.w, accp[r2][3]);
        *(float4*)(ob + (m0 + row + 2 * r2 + 0) * 128 + col) = vlo;
        *(float4*)(ob + (m0 + row + 2 * r2 + 1) * 128 + col) = vhi;
    }
}

// ---------------------------------------------------------------------------
// Edge MLP in CSR order: consecutive slots share dst -> B row stays L1-hot.
// h = relu(A[src] + B[dst] + b1);  out[eid] = sigmoid(h . w2 + b2)
// One warp per CSR slot; each lane owns 4 of 128 hidden dims.
// ---------------------------------------------------------------------------
__global__ void k_mlp(const float* __restrict__ b1, const float* __restrict__ w2,
                      const float* __restrict__ b2, float* __restrict__ out) {
    int warp = (blockIdx.x * blockDim.x + threadIdx.x) >> 5;
    int lane = threadIdx.x & 31;
    if (warp >= EE) return;
    int p = warp;
    int s = g_ssrc[p], d = g_sdst[p], e = g_seid[p];
    float4 a  = ((const float4*)(g_A + s * 128))[lane];
    float4 b  = ((const float4*)(g_B + d * 128))[lane];
    float4 bb = ((const float4*)b1)[lane];
    float4 w  = ((const float4*)w2)[lane];
    float hx = fmaxf(a.x + b.x + bb.x, 0.f);
    float hy = fmaxf(a.y + b.y + bb.y, 0.f);
    float hz = fmaxf(a.z + b.z + bb.z, 0.f);
    float hw = fmaxf(a.w + b.w + bb.w, 0.f);
    float z = hx * w.x + hy * w.y + hz * w.z + hw * w.w;
#pragma unroll
    for (int off = 16; off; off >>= 1)
        z += __shfl_xor_sync(0xffffffffu, z, off);
    if (lane == 0) {
        z += __ldg(b2);
        out[e] = 1.f / (1.f + __expf(-z));
    }
}

// ---------------------------------------------------------------------------
// Launch — robust input binding by element count (edge_index: 2*EE ints,
// edge_type: EE ints; remaining 24 float inputs keep relative order).
// All kernel arguments derive from d_in/d_out only — never device symbols.
// ---------------------------------------------------------------------------
extern "C" void kernel_launch(void* const* d_in, const int* in_sizes, int n_in,
                              void* d_out, int out_size) {
    int ei_idx = -1, et_idx = -1;
    for (int i = 0; i < n_in; i++) {
        if (in_sizes[i] == 2 * EE) ei_idx = i;
        else if (in_sizes[i] == EE) et_idx = i;
    }
    const float* rest[24];
    int k = 0;
    for (int i = 0; i < n_in && k < 24; i++) {
        if (i == ei_idx || i == et_idx) continue;
        rest[k++] = (const float*)d_in[i];
    }

    const int* edge_index = (const int*)d_in[ei_idx];
    const int* src = edge_index;
    const int* dst = edge_index + EE;
    const int* etype = (const int*)d_in[et_idx];

    const float* basis[4] = {rest[0], rest[4], rest[8],  rest[12]};
    const float* comp[4]  = {rest[1], rest[5], rest[9],  rest[13]};
    const float* root[4]  = {rest[2], rest[6], rest[10], rest[14]};
    const float* rbias[4] = {rest[3], rest[7], rest[11], rest[15]};
    const float* gat_w   = rest[16];
    const float* att_src = rest[17];
    const float* att_dst = rest[18];
    const float* gat_b   = rest[19];
    const float* w1 = rest[20];
    const float* b1 = rest[21];
    const float* w2 = rest[22];
    const float* b2 = rest[23];
    float* out = (float*)d_out;

    const int TB = 256;
    const int PREP = 2 * NN * 32 + 6144 + 12288 + 6144 + EE;
    k_prep<<<(PREP + TB - 1) / TB, TB>>>(basis[0], comp[0],
                                         basis[1], comp[1], root[1],
                                         basis[2], comp[2], root[2],
                                         basis[3], comp[3], root[3],
                                         dst);
    k_scan<<<1, 256>>>();
    k_scatter<<<(EE + TB - 1) / TB, TB>>>(src, dst, etype);

    // Layer 0 + HR1 -> g_HRa
    k_l0<<<(NN * 32 + TB - 1) / TB, TB>>>(root[0], rbias[0]);
    // agg1 + HR2 : g_HRa -> g_HRb
    k_agg64<192, 6, true><<<(NN * 32 + TB - 1) / TB, TB>>>(rbias[1], WC2_OFF);
    // agg2 + HR3 : g_HRb -> g_HRa (J=96)
    k_agg64<96, 3, false><<<(NN * 32 + TB - 1) / TB, TB>>>(rbias[2], WC3_OFF);

    // agg3 + GAT h + attdot (fused)
    k_gath3<<<NN / 4, 128>>>(rbias[3], gat_w, att_src, att_dst);
    // GAT softmax + aggregate
    k_gatsm<<<NN, 128>>>(gat_b);

    // Edge MLP via per-node precomputation
    dim3 gab(NNP / 64, 2);
    k_ab<<<gab, 256>>>(w1);
    k_mlp<<<(EE * 32 + TB - 1) / TB, TB>>>(b1, w2, b2, out);
}